// round 7
// baseline (speedup 1.0000x reference)
#include <cuda_runtime.h>
#include <cstdint>

typedef unsigned long long u64;

#define NQ   4
#define PROJ 64
#define TPB  256
#define WARPS (TPB/32)
#define GRID 592

// ---------------- f32x2 helpers (Blackwell packed fp32) ----------------
__device__ __forceinline__ u64 pk(float lo, float hi) {
    u64 r; asm("mov.b64 %0, {%1, %2};" : "=l"(r) : "f"(lo), "f"(hi)); return r;
}
__device__ __forceinline__ float2 upk(u64 v) {
    float2 r; asm("mov.b64 {%0, %1}, %2;" : "=f"(r.x), "=f"(r.y) : "l"(v)); return r;
}
__device__ __forceinline__ u64 fma2(u64 a, u64 b, u64 c) {
    u64 d; asm("fma.rn.f32x2 %0, %1, %2, %3;" : "=l"(d) : "l"(a), "l"(b), "l"(c)); return d;
}

// ---------------- single fused kernel ----------------
// Prologue (per block, identical work in every block): build
//   sC[81]  : coefficient tensor, packed {(z0,z1),(z2,z3)} per e-index
//   sK[26]  : LN quadratic-form constants (u pre-doubled at 16..19)
//   sPC[16][5] : folded projection/LN/affine table for phase 2
// Main loop: grid-stride over 32-sample chunks.
__global__ void __launch_bounds__(TPB, 4)
quantum_kernel(const float* __restrict__ x,
               const float* __restrict__ weights,
               const float* __restrict__ W,
               const float* __restrict__ b,
               const float* __restrict__ gamma,
               const float* __restrict__ beta,
               float* __restrict__ out, int Bn)
{
    __shared__ float2 sM[8][4];
    __shared__ float sVr[16][16];
    __shared__ float sVi[16][16];
    __shared__ float sgc[32];
    __shared__ __align__(16) u64 bufA[512];
    __shared__ __align__(16) u64 bufB[384];
    __shared__ __align__(16) ulonglong2 sC[81];
    __shared__ float sK[26];
    __shared__ __align__(16) ulonglong2 sPC[16][5];
    __shared__ __align__(16) u64 s_q[WARPS][32][4];

    const int tid  = threadIdx.x;
    const int lane = tid & 31;
    const int wid  = tid >> 5;

    // ================= PROLOGUE =================
    if (tid < 8) {
        int l = tid >> 2, w = tid & 3;
        float phi = weights[l * 12 + w * 3 + 0];
        float th  = weights[l * 12 + w * 3 + 1];
        float om  = weights[l * 12 + w * 3 + 2];
        float c, s; sincosf(0.5f * th, &s, &c);
        float ap = -0.5f * (phi + om);
        float am =  0.5f * (phi - om);
        float cap, sap, cam, sam;
        sincosf(ap, &sap, &cap);
        sincosf(am, &sam, &cam);
        sM[tid][0] = make_float2( c * cap,  c * sap);
        sM[tid][1] = make_float2(-s * cam, -s * sam);
        sM[tid][2] = make_float2( s * cam, -s * sam);
        sM[tid][3] = make_float2( c * cap, -c * sap);
    }
    __syncthreads();

    // V columns (16 threads) — V = U_ent * diag((-i)^popcount)
    if (tid < 16) {
        const int j = tid;
        float ar[16], ai[16];
        #pragma unroll
        for (int o = 0; o < 16; o++) { ar[o] = (o == j) ? 1.f : 0.f; ai[o] = 0.f; }
        #pragma unroll
        for (int l = 0; l < 2; l++) {
            #pragma unroll
            for (int w = 0; w < NQ; w++) {
                int g = l * 4 + w;
                float2 M00 = sM[g][0], M01 = sM[g][1], M10 = sM[g][2], M11 = sM[g][3];
                int mask = 8 >> w;
                #pragma unroll
                for (int k = 0; k < 16; k++) if (!(k & mask)) {
                    int k1 = k | mask;
                    float a0r = ar[k],  a0i = ai[k];
                    float a1r = ar[k1], a1i = ai[k1];
                    ar[k]  = M00.x*a0r - M00.y*a0i + M01.x*a1r - M01.y*a1i;
                    ai[k]  = M00.x*a0i + M00.y*a0r + M01.x*a1i + M01.y*a1r;
                    ar[k1] = M10.x*a0r - M10.y*a0i + M11.x*a1r - M11.y*a1i;
                    ai[k1] = M10.x*a0i + M10.y*a0r + M11.x*a1i + M11.y*a1r;
                }
            }
            int rr = (l % 3) + 1;
            #pragma unroll
            for (int w = 0; w < NQ; w++) {
                int cm = 8 >> w, tm = 8 >> ((w + rr) & 3);
                #pragma unroll
                for (int k = 0; k < 16; k++) if ((k & cm) && !(k & tm)) {
                    int k1 = k | tm;
                    float tr = ar[k], ti = ai[k];
                    ar[k] = ar[k1];  ai[k] = ai[k1];
                    ar[k1] = tr;     ai[k1] = ti;
                }
            }
        }
        int pc = __popc(j) & 3;
        float fr = (pc == 0) ? 1.f : ((pc == 2) ? -1.f : 0.f);
        float fi = (pc == 1) ? -1.f : ((pc == 3) ? 1.f : 0.f);
        #pragma unroll
        for (int o = 0; o < 16; o++) {
            sVr[o][j] = ar[o] * fr - ai[o] * fi;
            sVi[o][j] = ar[o] * fi + ai[o] * fr;
        }
    }

    // warp 1: projection / LN constants
    if (tid >= 32 && tid < 64) {
        int ln = tid - 32;
        float A[16], u4[4], wb[4], e = 0.f, bb = 0.f;
        #pragma unroll
        for (int i = 0; i < 16; i++) A[i] = 0.f;
        #pragma unroll
        for (int i = 0; i < 4; i++) { u4[i] = 0.f; wb[i] = 0.f; }
        #pragma unroll
        for (int rep = 0; rep < 2; rep++) {
            int r = ln + rep * 32;
            float4 wr = *(const float4*)(W + r * 4);
            float br = b[r];
            float wv[4] = {wr.x, wr.y, wr.z, wr.w};
            #pragma unroll
            for (int i = 0; i < 4; i++) {
                #pragma unroll
                for (int jj = 0; jj < 4; jj++) A[i * 4 + jj] += wv[i] * wv[jj];
                u4[i] += wv[i] * br;
                wb[i] += wv[i];
            }
            e += br * br; bb += br;
        }
        #pragma unroll
        for (int off = 16; off > 0; off >>= 1) {
            #pragma unroll
            for (int i = 0; i < 16; i++) A[i] += __shfl_xor_sync(0xffffffffu, A[i], off);
            #pragma unroll
            for (int i = 0; i < 4; i++) {
                u4[i] += __shfl_xor_sync(0xffffffffu, u4[i], off);
                wb[i] += __shfl_xor_sync(0xffffffffu, wb[i], off);
            }
            e  += __shfl_xor_sync(0xffffffffu, e, off);
            bb += __shfl_xor_sync(0xffffffffu, bb, off);
        }
        if (ln == 0) {
            const float inv = 1.f / 64.f;
            #pragma unroll
            for (int i = 0; i < 16; i++) sgc[i] = A[i] * inv;
            #pragma unroll
            for (int i = 0; i < 4; i++) {
                sgc[16 + i] = u4[i] * inv;
                sgc[21 + i] = wb[i] * inv;
            }
            sgc[20] = e * inv;
            sgc[25] = bb * inv;
        }
    }
    __syncthreads();

    // S_w[j][k] -> pair-radix layout in bufA
    {
        int j = tid >> 4, k = tid & 15;
        float a0 = 0.f, a1 = 0.f, a2 = 0.f, a3 = 0.f;
        #pragma unroll
        for (int o = 0; o < 16; o++) {
            float d = sVr[o][j] * sVr[o][k] + sVi[o][j] * sVi[o][k];
            a0 += (o & 8) ? -d : d;
            a1 += (o & 4) ? -d : d;
            a2 += (o & 2) ? -d : d;
            a3 += (o & 1) ? -d : d;
        }
        int p0 = 2 * ((j >> 3) & 1) + ((k >> 3) & 1);
        int p1 = 2 * ((j >> 2) & 1) + ((k >> 2) & 1);
        int p2 = 2 * ((j >> 1) & 1) + ((k >> 1) & 1);
        int p3 = 2 * (j & 1) + (k & 1);
        int idx = ((p0 * 4 + p1) * 4 + p2) * 4 + p3;
        bufA[idx * 2 + 0] = pk(a0, a1);
        bufA[idx * 2 + 1] = pk(a2, a3);
    }
    __syncthreads();

    // 4 per-wire contractions: radix-4 pair -> radix-3 (1,cos,sin)
    {
        const int pow3[4] = {1, 3, 9, 27};
        const int P4s[4]  = {64, 16, 4, 1};
        for (int s = 0; s < 4; s++) {
            u64* In  = (s & 1) ? bufB : bufA;
            u64* Out = (s & 1) ? bufA : bufB;
            int P4 = P4s[s];
            int nitems = pow3[s] * P4 * 2;
            if (tid < nitems) {
                int pack = tid & 1, i = tid >> 1;
                int E = i / P4, P = i % P4;
                float2 v0 = upk(In[((E * 4 + 0) * P4 + P) * 2 + pack]);
                float2 v1 = upk(In[((E * 4 + 1) * P4 + P) * 2 + pack]);
                float2 v2 = upk(In[((E * 4 + 2) * P4 + P) * 2 + pack]);
                float2 v3 = upk(In[((E * 4 + 3) * P4 + P) * 2 + pack]);
                Out[((E * 3 + 0) * P4 + P) * 2 + pack] = pk(0.5f*(v0.x+v3.x), 0.5f*(v0.y+v3.y));
                Out[((E * 3 + 1) * P4 + P) * 2 + pack] = pk(0.5f*(v0.x-v3.x), 0.5f*(v0.y-v3.y));
                Out[((E * 3 + 2) * P4 + P) * 2 + pack] = pk(0.5f*(v1.x+v2.x), 0.5f*(v1.y+v2.y));
            }
            __syncthreads();
        }
    }
    // finalize tables in smem
    if (tid < 162) {   // sC, transposed so e0 is innermost
        int pack = tid & 1, i = tid >> 1;
        int e3 = i % 3, e2 = (i / 3) % 3, e1 = (i / 9) % 3, e0 = i / 27;
        int outi = ((e3 * 3 + e2) * 3 + e1) * 3 + e0;
        ((u64*)sC)[outi * 2 + pack] = bufA[i * 2 + pack];
    }
    if (tid >= 192 && tid < 208) {   // sPC: folded projection table, 4 cols per entry
        int g = tid - 192;
        float bb = sgc[25];
        u64 Gl[4], Gh[4];
        #pragma unroll
        for (int h = 0; h < 2; h++) {
            int j0 = 4 * g + 2 * h, j1 = j0 + 1;
            float b0 = b[j0], b1 = b[j1];
            float g0 = gamma[j0], g1 = gamma[j1];
            #pragma unroll
            for (int i = 0; i < 4; i++) {
                float wb = sgc[21 + i];
                float w0 = W[j0 * 4 + i] - wb + b0 - bb;
                float w1 = W[j1 * 4 + i] - wb + b1 - bb;
                if (h == 0) Gl[i] = pk(g0 * w0, g1 * w1);
                else        Gh[i] = pk(g0 * w0, g1 * w1);
            }
        }
        sPC[g][0] = make_ulonglong2(Gl[0], Gl[1]);
        sPC[g][1] = make_ulonglong2(Gl[2], Gl[3]);
        sPC[g][2] = make_ulonglong2(Gh[0], Gh[1]);
        sPC[g][3] = make_ulonglong2(Gh[2], Gh[3]);
        sPC[g][4] = make_ulonglong2(pk(beta[4*g], beta[4*g+1]), pk(beta[4*g+2], beta[4*g+3]));
    }
    if (tid >= 224 && tid < 250) {   // sK (u doubled)
        int i = tid - 224;
        float v = sgc[i];
        if (i >= 16 && i < 20) v = 2.f * v;
        sK[i] = v;
    }
    __syncthreads();

    // ================= MAIN LOOP =================
    const int g4 = lane & 15;
    const int p  = lane >> 4;
    const int jcol = 4 * g4;
    const int warp_global = blockIdx.x * WARPS + wid;
    const int nwarps  = GRID * WARPS;
    const int nchunks = Bn >> 5;

    int chunk = warp_global;
    bool valid = chunk < nchunks;
    float4 xv;
    if (valid) xv = *(const float4*)(x + ((size_t)(chunk << 5) + lane) * 4);

    while (valid) {
        const int base = chunk << 5;

        // ---- phase 1: one sample per lane ----
        float xs[4] = {xv.x, xv.y, xv.z, xv.w};
        u64 cp[4], sp[4];
        #pragma unroll
        for (int w = 0; w < 4; w++) {
            float t  = __expf(xs[w] + xs[w]);
            float th = 1.f - __fdividef(2.f, t + 1.f);        // tanh
            float sn, cs;
            __sincosf(3.14159265358979323846f * th, &sn, &cs);
            cp[w] = pk(cs, cs);
            sp[w] = pk(sn, sn);
        }

        // prefetch next chunk's x while the contraction runs
        const int next = chunk + nwarps;
        const bool nvalid = next < nchunks;
        float4 xn;
        if (nvalid) xn = *(const float4*)(x + ((size_t)(next << 5) + lane) * 4);

        // z = sum_e C[e] * prod_w (1,cos,sin)_{e_w}
        u64 z01 = 0ull, z23 = 0ull;
        #pragma unroll
        for (int e3 = 0; e3 < 3; e3++) {
            u64 a3_01, a3_23;
            #pragma unroll
            for (int e2 = 0; e2 < 3; e2++) {
                u64 a2_01, a2_23;
                #pragma unroll
                for (int e1 = 0; e1 < 3; e1++) {
                    int cbase = ((e3 * 3 + e2) * 3 + e1) * 3;
                    ulonglong2 C0 = sC[cbase];
                    ulonglong2 C1 = sC[cbase + 1];
                    ulonglong2 C2 = sC[cbase + 2];
                    u64 t01 = fma2(cp[0], C1.x, C0.x); t01 = fma2(sp[0], C2.x, t01);
                    u64 t23 = fma2(cp[0], C1.y, C0.y); t23 = fma2(sp[0], C2.y, t23);
                    if (e1 == 0)      { a2_01 = t01;                   a2_23 = t23; }
                    else if (e1 == 1) { a2_01 = fma2(cp[1], t01, a2_01); a2_23 = fma2(cp[1], t23, a2_23); }
                    else              { a2_01 = fma2(sp[1], t01, a2_01); a2_23 = fma2(sp[1], t23, a2_23); }
                }
                if (e2 == 0)      { a3_01 = a2_01;                    a3_23 = a2_23; }
                else if (e2 == 1) { a3_01 = fma2(cp[2], a2_01, a3_01); a3_23 = fma2(cp[2], a2_23, a3_23); }
                else              { a3_01 = fma2(sp[2], a2_01, a3_01); a3_23 = fma2(sp[2], a2_23, a3_23); }
            }
            if (e3 == 0)      { z01 = a3_01;                    z23 = a3_23; }
            else if (e3 == 1) { z01 = fma2(cp[3], a3_01, z01);  z23 = fma2(cp[3], a3_23, z23); }
            else              { z01 = fma2(sp[3], a3_01, z01);  z23 = fma2(sp[3], a3_23, z23); }
        }
        float2 zA = upk(z01), zB = upk(z23);

        // softmax (z in [-1,1], no max-shift needed)
        float q0 = __expf(zA.x), q1 = __expf(zA.y), q2 = __expf(zB.x), q3 = __expf(zB.y);
        float inv = __fdividef(1.f, (q0 + q1) + (q2 + q3));
        q0 *= inv; q1 *= inv; q2 *= inv; q3 *= inv;
        float qa[4] = {q0, q1, q2, q3};

        // LN stats via precomputed quadratic forms
        float mu = sK[25];
        #pragma unroll
        for (int i = 0; i < 4; i++) mu = fmaf(sK[21 + i], qa[i], mu);
        float eh2 = sK[20];
        #pragma unroll
        for (int i = 0; i < 4; i++) {
            float ti = sK[16 + i];                // 2u_i (pre-doubled)
            #pragma unroll
            for (int jj = 0; jj < 4; jj++) ti = fmaf(sK[i * 4 + jj], qa[jj], ti);
            eh2 = fmaf(qa[i], ti, eh2);
        }
        float var = fmaf(-mu, mu, eh2);
        float rs = rsqrtf(var + 1e-5f);

        // store rs-scaled q, replicated {v,v}
        {
            float a0 = q0 * rs, a1 = q1 * rs, a2 = q2 * rs, a3 = q3 * rs;
            ulonglong2* dst = (ulonglong2*)&s_q[wid][lane][0];
            dst[0] = make_ulonglong2(pk(a0, a0), pk(a1, a1));
            dst[1] = make_ulonglong2(pk(a2, a2), pk(a3, a3));
        }
        __syncwarp();

        // ---- phase 2: half-warp per row, 4 cols/lane, STG.128 ----
        {
            ulonglong2 A0 = sPC[g4][0], A1 = sPC[g4][1];
            ulonglong2 B0 = sPC[g4][2], B1 = sPC[g4][3];
            ulonglong2 BB = sPC[g4][4];
            #pragma unroll 4
            for (int r = 0; r < 16; r++) {
                const int row = 2 * r + p;
                const ulonglong2* qp = (const ulonglong2*)&s_q[wid][row][0];
                ulonglong2 qa2 = qp[0], qb2 = qp[1];
                u64 acc_lo = fma2(A0.x, qa2.x, BB.x);
                u64 acc_hi = fma2(B0.x, qa2.x, BB.y);
                acc_lo = fma2(A0.y, qa2.y, acc_lo);
                acc_hi = fma2(B0.y, qa2.y, acc_hi);
                acc_lo = fma2(A1.x, qb2.x, acc_lo);
                acc_hi = fma2(B1.x, qb2.x, acc_hi);
                acc_lo = fma2(A1.y, qb2.y, acc_lo);
                acc_hi = fma2(B1.y, qb2.y, acc_hi);
                float2 lo = upk(acc_lo), hi = upk(acc_hi);
                float4 ov = make_float4(lo.x, lo.y, hi.x, hi.y);
                *(float4*)(out + (size_t)(base + row) * PROJ + jcol) = ov;
            }
        }
        __syncwarp();

        xv = xn; chunk = next; valid = nvalid;
    }
}

extern "C" void kernel_launch(void* const* d_in, const int* in_sizes, int n_in,
                              void* d_out, int out_size)
{
    const float* x       = (const float*)d_in[0];
    const float* weights = (const float*)d_in[1];
    const float* W       = (const float*)d_in[2];
    const float* b       = (const float*)d_in[3];
    const float* gamma   = (const float*)d_in[4];
    const float* beta    = (const float*)d_in[5];
    float* out = (float*)d_out;
    int Bn = in_sizes[0] / NQ;

    quantum_kernel<<<GRID, TPB>>>(x, weights, W, b, gamma, beta, out, Bn);
}

// round 8
// speedup vs baseline: 1.0977x; 1.0977x over previous
#include <cuda_runtime.h>
#include <cstdint>

typedef unsigned long long u64;

#define NQ   4
#define PROJ 64
#define TPB  256
#define WARPS (TPB/32)
#define GRID 444

// ---------------- f32x2 helpers (Blackwell packed fp32) ----------------
__device__ __forceinline__ u64 pk(float lo, float hi) {
    u64 r; asm("mov.b64 %0, {%1, %2};" : "=l"(r) : "f"(lo), "f"(hi)); return r;
}
__device__ __forceinline__ float2 upk(u64 v) {
    float2 r; asm("mov.b64 {%0, %1}, %2;" : "=f"(r.x), "=f"(r.y) : "l"(v)); return r;
}
__device__ __forceinline__ u64 fma2(u64 a, u64 b, u64 c) {
    u64 d; asm("fma.rn.f32x2 %0, %1, %2, %3;" : "=l"(d) : "l"(a), "l"(b), "l"(c)); return d;
}

// ---------------- single fused kernel ----------------
__global__ void __launch_bounds__(TPB, 3)
quantum_kernel(const float* __restrict__ x,
               const float* __restrict__ weights,
               const float* __restrict__ W,
               const float* __restrict__ b,
               const float* __restrict__ gamma,
               const float* __restrict__ beta,
               float* __restrict__ out, int Bn)
{
    __shared__ float2 sM[8][4];
    __shared__ float sVr[16][16];
    __shared__ float sVi[16][16];
    __shared__ float sgc[32];
    __shared__ __align__(16) u64 bufA[512];
    __shared__ __align__(16) u64 bufB[384];
    __shared__ __align__(16) ulonglong2 sC[81];
    __shared__ float sK[26];
    __shared__ __align__(16) ulonglong2 sPC[16][5];
    __shared__ __align__(16) u64 s_q[WARPS][32][4];

    const int tid  = threadIdx.x;
    const int lane = tid & 31;
    const int wid  = tid >> 5;

    // ================= PROLOGUE (identical in every block) =================
    if (tid < 8) {
        int l = tid >> 2, w = tid & 3;
        float phi = weights[l * 12 + w * 3 + 0];
        float th  = weights[l * 12 + w * 3 + 1];
        float om  = weights[l * 12 + w * 3 + 2];
        float c, s; sincosf(0.5f * th, &s, &c);
        float ap = -0.5f * (phi + om);
        float am =  0.5f * (phi - om);
        float cap, sap, cam, sam;
        sincosf(ap, &sap, &cap);
        sincosf(am, &sam, &cam);
        sM[tid][0] = make_float2( c * cap,  c * sap);
        sM[tid][1] = make_float2(-s * cam, -s * sam);
        sM[tid][2] = make_float2( s * cam, -s * sam);
        sM[tid][3] = make_float2( c * cap, -c * sap);
    }
    __syncthreads();

    // V columns (16 threads) — V = U_ent * diag((-i)^popcount)
    if (tid < 16) {
        const int j = tid;
        float ar[16], ai[16];
        #pragma unroll
        for (int o = 0; o < 16; o++) { ar[o] = (o == j) ? 1.f : 0.f; ai[o] = 0.f; }
        #pragma unroll
        for (int l = 0; l < 2; l++) {
            #pragma unroll
            for (int w = 0; w < NQ; w++) {
                int g = l * 4 + w;
                float2 M00 = sM[g][0], M01 = sM[g][1], M10 = sM[g][2], M11 = sM[g][3];
                int mask = 8 >> w;
                #pragma unroll
                for (int k = 0; k < 16; k++) if (!(k & mask)) {
                    int k1 = k | mask;
                    float a0r = ar[k],  a0i = ai[k];
                    float a1r = ar[k1], a1i = ai[k1];
                    ar[k]  = M00.x*a0r - M00.y*a0i + M01.x*a1r - M01.y*a1i;
                    ai[k]  = M00.x*a0i + M00.y*a0r + M01.x*a1i + M01.y*a1r;
                    ar[k1] = M10.x*a0r - M10.y*a0i + M11.x*a1r - M11.y*a1i;
                    ai[k1] = M10.x*a0i + M10.y*a0r + M11.x*a1i + M11.y*a1r;
                }
            }
            int rr = (l % 3) + 1;
            #pragma unroll
            for (int w = 0; w < NQ; w++) {
                int cm = 8 >> w, tm = 8 >> ((w + rr) & 3);
                #pragma unroll
                for (int k = 0; k < 16; k++) if ((k & cm) && !(k & tm)) {
                    int k1 = k | tm;
                    float tr = ar[k], ti = ai[k];
                    ar[k] = ar[k1];  ai[k] = ai[k1];
                    ar[k1] = tr;     ai[k1] = ti;
                }
            }
        }
        int pc = __popc(j) & 3;
        float fr = (pc == 0) ? 1.f : ((pc == 2) ? -1.f : 0.f);
        float fi = (pc == 1) ? -1.f : ((pc == 3) ? 1.f : 0.f);
        #pragma unroll
        for (int o = 0; o < 16; o++) {
            sVr[o][j] = ar[o] * fr - ai[o] * fi;
            sVi[o][j] = ar[o] * fi + ai[o] * fr;
        }
    }

    // warp 1: projection / LN constants
    if (tid >= 32 && tid < 64) {
        int ln = tid - 32;
        float A[16], u4[4], wb[4], e = 0.f, bb = 0.f;
        #pragma unroll
        for (int i = 0; i < 16; i++) A[i] = 0.f;
        #pragma unroll
        for (int i = 0; i < 4; i++) { u4[i] = 0.f; wb[i] = 0.f; }
        #pragma unroll
        for (int rep = 0; rep < 2; rep++) {
            int r = ln + rep * 32;
            float4 wr = *(const float4*)(W + r * 4);
            float br = b[r];
            float wv[4] = {wr.x, wr.y, wr.z, wr.w};
            #pragma unroll
            for (int i = 0; i < 4; i++) {
                #pragma unroll
                for (int jj = 0; jj < 4; jj++) A[i * 4 + jj] += wv[i] * wv[jj];
                u4[i] += wv[i] * br;
                wb[i] += wv[i];
            }
            e += br * br; bb += br;
        }
        #pragma unroll
        for (int off = 16; off > 0; off >>= 1) {
            #pragma unroll
            for (int i = 0; i < 16; i++) A[i] += __shfl_xor_sync(0xffffffffu, A[i], off);
            #pragma unroll
            for (int i = 0; i < 4; i++) {
                u4[i] += __shfl_xor_sync(0xffffffffu, u4[i], off);
                wb[i] += __shfl_xor_sync(0xffffffffu, wb[i], off);
            }
            e  += __shfl_xor_sync(0xffffffffu, e, off);
            bb += __shfl_xor_sync(0xffffffffu, bb, off);
        }
        if (ln == 0) {
            const float inv = 1.f / 64.f;
            #pragma unroll
            for (int i = 0; i < 16; i++) sgc[i] = A[i] * inv;
            #pragma unroll
            for (int i = 0; i < 4; i++) {
                sgc[16 + i] = u4[i] * inv;
                sgc[21 + i] = wb[i] * inv;
            }
            sgc[20] = e * inv;
            sgc[25] = bb * inv;
        }
    }
    __syncthreads();

    // S_w[j][k] -> pair-radix layout in bufA
    {
        int j = tid >> 4, k = tid & 15;
        float a0 = 0.f, a1 = 0.f, a2 = 0.f, a3 = 0.f;
        #pragma unroll
        for (int o = 0; o < 16; o++) {
            float d = sVr[o][j] * sVr[o][k] + sVi[o][j] * sVi[o][k];
            a0 += (o & 8) ? -d : d;
            a1 += (o & 4) ? -d : d;
            a2 += (o & 2) ? -d : d;
            a3 += (o & 1) ? -d : d;
        }
        int p0 = 2 * ((j >> 3) & 1) + ((k >> 3) & 1);
        int p1 = 2 * ((j >> 2) & 1) + ((k >> 2) & 1);
        int p2 = 2 * ((j >> 1) & 1) + ((k >> 1) & 1);
        int p3 = 2 * (j & 1) + (k & 1);
        int idx = ((p0 * 4 + p1) * 4 + p2) * 4 + p3;
        bufA[idx * 2 + 0] = pk(a0, a1);
        bufA[idx * 2 + 1] = pk(a2, a3);
    }
    __syncthreads();

    // 4 per-wire contractions: radix-4 pair -> radix-3 (1,cos,sin)
    {
        const int pow3[4] = {1, 3, 9, 27};
        const int P4s[4]  = {64, 16, 4, 1};
        for (int s = 0; s < 4; s++) {
            u64* In  = (s & 1) ? bufB : bufA;
            u64* Out = (s & 1) ? bufA : bufB;
            int P4 = P4s[s];
            int nitems = pow3[s] * P4 * 2;
            if (tid < nitems) {
                int pack = tid & 1, i = tid >> 1;
                int E = i / P4, P = i % P4;
                float2 v0 = upk(In[((E * 4 + 0) * P4 + P) * 2 + pack]);
                float2 v1 = upk(In[((E * 4 + 1) * P4 + P) * 2 + pack]);
                float2 v2 = upk(In[((E * 4 + 2) * P4 + P) * 2 + pack]);
                float2 v3 = upk(In[((E * 4 + 3) * P4 + P) * 2 + pack]);
                Out[((E * 3 + 0) * P4 + P) * 2 + pack] = pk(0.5f*(v0.x+v3.x), 0.5f*(v0.y+v3.y));
                Out[((E * 3 + 1) * P4 + P) * 2 + pack] = pk(0.5f*(v0.x-v3.x), 0.5f*(v0.y-v3.y));
                Out[((E * 3 + 2) * P4 + P) * 2 + pack] = pk(0.5f*(v1.x+v2.x), 0.5f*(v1.y+v2.y));
            }
            __syncthreads();
        }
    }
    // finalize tables in smem
    if (tid < 162) {   // sC, transposed so e0 is innermost
        int pack = tid & 1, i = tid >> 1;
        int e3 = i % 3, e2 = (i / 3) % 3, e1 = (i / 9) % 3, e0 = i / 27;
        int outi = ((e3 * 3 + e2) * 3 + e1) * 3 + e0;
        ((u64*)sC)[outi * 2 + pack] = bufA[i * 2 + pack];
    }
    if (tid >= 192 && tid < 208) {   // sPC: folded projection table, 4 cols per entry
        int g = tid - 192;
        float bb = sgc[25];
        u64 Gl[4], Gh[4];
        #pragma unroll
        for (int h = 0; h < 2; h++) {
            int j0 = 4 * g + 2 * h, j1 = j0 + 1;
            float b0 = b[j0], b1 = b[j1];
            float g0 = gamma[j0], g1 = gamma[j1];
            #pragma unroll
            for (int i = 0; i < 4; i++) {
                float wb = sgc[21 + i];
                float w0 = W[j0 * 4 + i] - wb + b0 - bb;
                float w1 = W[j1 * 4 + i] - wb + b1 - bb;
                if (h == 0) Gl[i] = pk(g0 * w0, g1 * w1);
                else        Gh[i] = pk(g0 * w0, g1 * w1);
            }
        }
        sPC[g][0] = make_ulonglong2(Gl[0], Gl[1]);
        sPC[g][1] = make_ulonglong2(Gl[2], Gl[3]);
        sPC[g][2] = make_ulonglong2(Gh[0], Gh[1]);
        sPC[g][3] = make_ulonglong2(Gh[2], Gh[3]);
        sPC[g][4] = make_ulonglong2(pk(beta[4*g], beta[4*g+1]), pk(beta[4*g+2], beta[4*g+3]));
    }
    if (tid >= 224 && tid < 250) {   // sK (u doubled)
        int i = tid - 224;
        float v = sgc[i];
        if (i >= 16 && i < 20) v = 2.f * v;
        sK[i] = v;
    }
    __syncthreads();

    // ================= MAIN LOOP =================
    const int g4 = lane & 15;
    const int p  = lane >> 4;
    const int jcol = 4 * g4;

    // phase-2 constants into registers for the whole main loop
    ulonglong2 A0 = sPC[g4][0], A1 = sPC[g4][1];
    ulonglong2 B0 = sPC[g4][2], B1 = sPC[g4][3];
    ulonglong2 BB = sPC[g4][4];

    const int warp_global = blockIdx.x * WARPS + wid;
    const int nwarps  = GRID * WARPS;
    const int nchunks = Bn >> 5;

    for (int chunk = warp_global; chunk < nchunks; chunk += nwarps) {
        const int base = chunk << 5;
        const int s = base + lane;

        // ---- phase 1: one sample per lane ----
        float4 xv = *(const float4*)(x + (size_t)s * 4);
        float xs[4] = {xv.x, xv.y, xv.z, xv.w};
        u64 cp[4], sp[4];
        #pragma unroll
        for (int w = 0; w < 4; w++) {
            float t  = __expf(xs[w] + xs[w]);
            float th = 1.f - __fdividef(2.f, t + 1.f);        // tanh
            float sn, cs;
            __sincosf(3.14159265358979323846f * th, &sn, &cs);
            cp[w] = pk(cs, cs);
            sp[w] = pk(sn, sn);
        }

        // z = sum_e C[e] * prod_w (1,cos,sin)_{e_w}
        u64 z01 = 0ull, z23 = 0ull;
        #pragma unroll
        for (int e3 = 0; e3 < 3; e3++) {
            u64 a3_01, a3_23;
            #pragma unroll
            for (int e2 = 0; e2 < 3; e2++) {
                u64 a2_01, a2_23;
                #pragma unroll
                for (int e1 = 0; e1 < 3; e1++) {
                    int cbase = ((e3 * 3 + e2) * 3 + e1) * 3;
                    ulonglong2 C0 = sC[cbase];
                    ulonglong2 C1 = sC[cbase + 1];
                    ulonglong2 C2 = sC[cbase + 2];
                    u64 t01 = fma2(cp[0], C1.x, C0.x); t01 = fma2(sp[0], C2.x, t01);
                    u64 t23 = fma2(cp[0], C1.y, C0.y); t23 = fma2(sp[0], C2.y, t23);
                    if (e1 == 0)      { a2_01 = t01;                   a2_23 = t23; }
                    else if (e1 == 1) { a2_01 = fma2(cp[1], t01, a2_01); a2_23 = fma2(cp[1], t23, a2_23); }
                    else              { a2_01 = fma2(sp[1], t01, a2_01); a2_23 = fma2(sp[1], t23, a2_23); }
                }
                if (e2 == 0)      { a3_01 = a2_01;                    a3_23 = a2_23; }
                else if (e2 == 1) { a3_01 = fma2(cp[2], a2_01, a3_01); a3_23 = fma2(cp[2], a2_23, a3_23); }
                else              { a3_01 = fma2(sp[2], a2_01, a3_01); a3_23 = fma2(sp[2], a2_23, a3_23); }
            }
            if (e3 == 0)      { z01 = a3_01;                    z23 = a3_23; }
            else if (e3 == 1) { z01 = fma2(cp[3], a3_01, z01);  z23 = fma2(cp[3], a3_23, z23); }
            else              { z01 = fma2(sp[3], a3_01, z01);  z23 = fma2(sp[3], a3_23, z23); }
        }
        float2 zA = upk(z01), zB = upk(z23);

        // softmax (z in [-1,1], no max-shift needed)
        float q0 = __expf(zA.x), q1 = __expf(zA.y), q2 = __expf(zB.x), q3 = __expf(zB.y);
        float inv = __fdividef(1.f, (q0 + q1) + (q2 + q3));
        q0 *= inv; q1 *= inv; q2 *= inv; q3 *= inv;
        float qa[4] = {q0, q1, q2, q3};

        // LN stats via precomputed quadratic forms
        float mu = sK[25];
        #pragma unroll
        for (int i = 0; i < 4; i++) mu = fmaf(sK[21 + i], qa[i], mu);
        float eh2 = sK[20];
        #pragma unroll
        for (int i = 0; i < 4; i++) {
            float ti = sK[16 + i];                // 2u_i (pre-doubled)
            #pragma unroll
            for (int jj = 0; jj < 4; jj++) ti = fmaf(sK[i * 4 + jj], qa[jj], ti);
            eh2 = fmaf(qa[i], ti, eh2);
        }
        float var = fmaf(-mu, mu, eh2);
        float rs = rsqrtf(var + 1e-5f);

        // store rs-scaled q, replicated {v,v}
        {
            float a0 = q0 * rs, a1 = q1 * rs, a2 = q2 * rs, a3 = q3 * rs;
            ulonglong2* dst = (ulonglong2*)&s_q[wid][lane][0];
            dst[0] = make_ulonglong2(pk(a0, a0), pk(a1, a1));
            dst[1] = make_ulonglong2(pk(a2, a2), pk(a3, a3));
        }
        __syncwarp();

        // ---- phase 2: half-warp per row, 4 cols/lane, STG.128 ----
        #pragma unroll 4
        for (int r = 0; r < 16; r++) {
            const int row = 2 * r + p;
            const ulonglong2* qp = (const ulonglong2*)&s_q[wid][row][0];
            ulonglong2 qa2 = qp[0], qb2 = qp[1];
            u64 acc_lo = fma2(A0.x, qa2.x, BB.x);
            u64 acc_hi = fma2(B0.x, qa2.x, BB.y);
            acc_lo = fma2(A0.y, qa2.y, acc_lo);
            acc_hi = fma2(B0.y, qa2.y, acc_hi);
            acc_lo = fma2(A1.x, qb2.x, acc_lo);
            acc_hi = fma2(B1.x, qb2.x, acc_hi);
            acc_lo = fma2(A1.y, qb2.y, acc_lo);
            acc_hi = fma2(B1.y, qb2.y, acc_hi);
            float2 lo = upk(acc_lo), hi = upk(acc_hi);
            float4 ov = make_float4(lo.x, lo.y, hi.x, hi.y);
            *(float4*)(out + (size_t)(base + row) * PROJ + jcol) = ov;
        }
        __syncwarp();
    }
}

extern "C" void kernel_launch(void* const* d_in, const int* in_sizes, int n_in,
                              void* d_out, int out_size)
{
    const float* x       = (const float*)d_in[0];
    const float* weights = (const float*)d_in[1];
    const float* W       = (const float*)d_in[2];
    const float* b       = (const float*)d_in[3];
    const float* gamma   = (const float*)d_in[4];
    const float* beta    = (const float*)d_in[5];
    float* out = (float*)d_out;
    int Bn = in_sizes[0] / NQ;

    quantum_kernel<<<GRID, TPB>>>(x, weights, W, b, gamma, beta, out, Bn);
}